// round 9
// baseline (speedup 1.0000x reference)
#include <cuda_runtime.h>

// Problem constants
#define NB   2
#define C    128
#define H    64
#define WID  64
#define HW   4096       // H*WID
#define KK   81         // L*L
#define PADR 4          // L/2

// sim kernel tiling (2x16 px tiles -> 256 blocks, 576 threads)
#define BTH  2
#define BTW  16
#define BTP  32         // px per tile
#define BHY  10         // 2 + 8 halo rows
#define BHX  24
#define BKST 28         // padded halo row stride
#define CCB  32         // channel chunk
#define BNT  576        // threads
#define SIMN 2592       // BTP*KK

// weighting kernel tiling (4x16 px tiles x 4 channel chunks -> 512 blocks)
#define TH   4
#define TW   16
#define TP   64
#define HY   12
#define HX   24
#define KST  28
#define CCD  32
#define WST  68

#define GK   16         // gemm W k-chunk
#define GO   64         // gemm o-rows per block

// Scratch (allocation-free rule: __device__ globals)
__device__ float g_key   [NB * C * HW];
__device__ float g_query [NB * C * HW];
__device__ float g_weight[NB * HW * KK];

// ---- packed fp32x2 helpers (sm_100+: ptxas never emits FFMA2 from C++) ----
typedef unsigned long long u64;
__device__ __forceinline__ u64 pk(float lo, float hi) {
    u64 r; asm("mov.b64 %0, {%1, %2};" : "=l"(r) : "f"(lo), "f"(hi)); return r;
}
__device__ __forceinline__ void fma2(u64& d, u64 a, u64 b) {
    asm("fma.rn.f32x2 %0, %1, %2, %0;" : "+l"(d) : "l"(a), "l"(b));
}
__device__ __forceinline__ float2 upk(u64 v) {
    float2 r; asm("mov.b64 {%0, %1}, %2;" : "=f"(r.x), "=f"(r.y) : "l"(v)); return r;
}

// ---------------------------------------------------------------------------
// Kernel A: 1x1-conv projections.  Y[o][p] = sum_i W[o][i] * X[i][p]
// grid = (64, 8): y = ohalf*4 + which*2 + n. 64-o x 64-px tiles -> 512 blocks
// (3.46/SM) for occupancy. X tile resident; W double-buffered 16-k chunks.
// ---------------------------------------------------------------------------
__global__ __launch_bounds__(256) void gemm_kernel(
        const float* __restrict__ ft, const float* __restrict__ fk,
        const float* __restrict__ Wm)
{
    extern __shared__ float sm[];
    float* Xs = sm;                 // [128][64]
    float* Ws = sm + 128 * 64;      // [2][GK][GO]

    const int t  = threadIdx.x;
    const int p0 = blockIdx.x * 64;
    const int y  = blockIdx.y;
    const int n  = y & 1;
    const int which = (y >> 1) & 1;
    const int o0 = (y >> 2) * GO;
    const float* X = (which ? fk : ft) + n * C * HW;
    float*       Y = (which ? g_query : g_key) + n * C * HW;

    const int px4 = (t & 15) * 4;
    const int oq  = (t >> 4) * 4;   // 4 o-rows per thread

    // load full X tile (8192 floats, 8 float4 per thread)
    {
        const int cc = t >> 4;
        const int xp = (t & 15) * 4;
        #pragma unroll
        for (int it = 0; it < 8; it++) {
            int c = cc + it * 16;
            *(float4*)&Xs[c * 64 + xp] = *(const float4*)&X[c * HW + p0 + xp];
        }
    }
    // stage W chunk (transposed: Ws[buf][kk][o64]); 4 floats per thread
    const int so = t >> 2;          // 0..63 o row within half
    const int k4 = (t & 3) * 4;
    auto stageW = [&](int buf, int kb) {
        float* Wb = Ws + buf * (GK * GO);
        float4 wv = *(const float4*)&Wm[(o0 + so) * C + kb + k4];
        Wb[(k4 + 0) * GO + so] = wv.x;
        Wb[(k4 + 1) * GO + so] = wv.y;
        Wb[(k4 + 2) * GO + so] = wv.z;
        Wb[(k4 + 3) * GO + so] = wv.w;
    };
    stageW(0, 0);

    u64 acc[2][4] = {};   // [o-pair][px]
    __syncthreads();

    int buf = 0;
    for (int kb = 0; kb < 8; kb++) {
        if (kb < 7) stageW(buf ^ 1, (kb + 1) * GK);
        const float* Wb = Ws + buf * (GK * GO);
        const float* Xb = Xs + (kb * GK) * 64;
        #pragma unroll
        for (int kk = 0; kk < GK; kk++) {
            float4 a = *(const float4*)&Wb[kk * GO + oq];
            float4 b = *(const float4*)&Xb[kk * 64 + px4];
            u64 ap0 = pk(a.x, a.y), ap1 = pk(a.z, a.w);
            u64 b0 = pk(b.x, b.x), b1 = pk(b.y, b.y);
            u64 b2 = pk(b.z, b.z), b3 = pk(b.w, b.w);
            fma2(acc[0][0], ap0, b0); fma2(acc[0][1], ap0, b1);
            fma2(acc[0][2], ap0, b2); fma2(acc[0][3], ap0, b3);
            fma2(acc[1][0], ap1, b0); fma2(acc[1][1], ap1, b1);
            fma2(acc[1][2], ap1, b2); fma2(acc[1][3], ap1, b3);
        }
        __syncthreads();
        buf ^= 1;
    }

    #pragma unroll
    for (int j2 = 0; j2 < 2; j2++) {
        float2 v0 = upk(acc[j2][0]), v1 = upk(acc[j2][1]);
        float2 v2 = upk(acc[j2][2]), v3 = upk(acc[j2][3]);
        *(float4*)&Y[(o0 + oq + 2 * j2)     * HW + p0 + px4] =
            make_float4(v0.x, v1.x, v2.x, v3.x);
        *(float4*)&Y[(o0 + oq + 2 * j2 + 1) * HW + p0 + px4] =
            make_float4(v0.y, v1.y, v2.y, v3.y);
    }
}

// ---------------------------------------------------------------------------
// Kernel B: sim (query . shifted key, zero-padded) + softmax over 81 taps.
// 256 blocks (2x16 px tiles), 576 threads (18 warps -> ~48% occ):
//   t -> (c8th = t/72, di = (t%72)/8, px-group = t%8)
// Each c8th accumulates 4 channels of each 32-channel chunk; partials merged
// pairwise into 4 smem arrays, then one tree pass. FFMA2 over px pairs.
// ---------------------------------------------------------------------------
__global__ __launch_bounds__(BNT) void sim_softmax_kernel()
{
    extern __shared__ float sm[];
    float* ks   = sm;                      // CCB*BHY*BKST = 8960 floats
    float* qs   = ks + CCB * BHY * BKST;   // CCB*BTP      = 1024
    float* simp = qs + CCB * BTP;          // 4*SIMN       = 10368

    const int t   = threadIdx.x;
    const int bx  = blockIdx.x;
    const int n   = bx >> 7;              // 128 tiles per image
    const int rem = bx & 127;
    const int ty0 = (rem >> 2) * BTH;
    const int tx0 = (rem & 3) * BTW;

    const float* keyg = g_key   + n * C * HW;
    const float* qg   = g_query + n * C * HW;

    const int cq  = t / 72;               // 0..7
    const int r   = t % 72;
    const int di  = r / 8;
    const int pxg = r % 8;
    const int ly  = pxg >> 2;             // 0..1
    const int lxg = (pxg & 3) * 4;

    u64 accp[9][2] = {};                  // [dj][px-pair]

    for (int cc = 0; cc < C; cc += CCB) {
        for (int i = t; i < CCB * BHY * BHX; i += BNT) {
            int hx = i % BHX;
            int hy = (i / BHX) % BHY;
            int c  = i / (BHX * BHY);
            int gy = ty0 + hy - PADR;
            int gx = tx0 + hx - PADR;
            float v = 0.f;
            if ((unsigned)gy < H && (unsigned)gx < WID)
                v = keyg[(cc + c) * HW + gy * WID + gx];
            ks[c * (BHY * BKST) + hy * BKST + hx] = v;
        }
        for (int i = t; i < CCB * BTP; i += BNT) {
            int px = i % BTP;
            int c  = i / BTP;
            qs[c * BTP + px] =
                qg[(cc + c) * HW + (ty0 + (px >> 4)) * WID + tx0 + (px & 15)];
        }
        __syncthreads();

        const int cbeg = cq * 4;
        #pragma unroll
        for (int c = cbeg; c < cbeg + 4; c++) {
            float4 q4 = *(const float4*)&qs[c * BTP + ly * BTW + lxg];
            const float* kp = &ks[c * (BHY * BKST) + (ly + di) * BKST + lxg];
            float4 k0 = *(const float4*)kp;
            float4 k1 = *(const float4*)(kp + 4);
            float4 k2 = *(const float4*)(kp + 8);
            const float kr[12] = {k0.x, k0.y, k0.z, k0.w,
                                  k1.x, k1.y, k1.z, k1.w,
                                  k2.x, k2.y, k2.z, k2.w};
            u64 q01 = pk(q4.x, q4.y), q23 = pk(q4.z, q4.w);
            u64 win[11];
            #pragma unroll
            for (int m = 0; m < 11; m++) win[m] = pk(kr[m], kr[m + 1]);
            #pragma unroll
            for (int dj = 0; dj < 9; dj++) {
                fma2(accp[dj][0], q01, win[dj]);
                fma2(accp[dj][1], q23, win[dj + 2]);
            }
        }
        __syncthreads();
    }

    // merge 8 partials: pairwise into 4 arrays, then 4->1 tree pass
    const int pxb = ly * BTW + lxg;
    float* sp = simp + (cq >> 1) * SIMN;
    if ((cq & 1) == 0) {
        #pragma unroll
        for (int dj = 0; dj < 9; dj++) {
            float2 v0 = upk(accp[dj][0]), v1 = upk(accp[dj][1]);
            sp[(pxb + 0) * KK + di * 9 + dj] = v0.x;
            sp[(pxb + 1) * KK + di * 9 + dj] = v0.y;
            sp[(pxb + 2) * KK + di * 9 + dj] = v1.x;
            sp[(pxb + 3) * KK + di * 9 + dj] = v1.y;
        }
    }
    __syncthreads();
    if (cq & 1) {
        #pragma unroll
        for (int dj = 0; dj < 9; dj++) {
            float2 v0 = upk(accp[dj][0]), v1 = upk(accp[dj][1]);
            sp[(pxb + 0) * KK + di * 9 + dj] += v0.x;
            sp[(pxb + 1) * KK + di * 9 + dj] += v0.y;
            sp[(pxb + 2) * KK + di * 9 + dj] += v1.x;
            sp[(pxb + 3) * KK + di * 9 + dj] += v1.y;
        }
    }
    __syncthreads();
    for (int i = t; i < SIMN; i += BNT)
        simp[i] = (simp[i] + simp[SIMN + i]) +
                  (simp[2 * SIMN + i] + simp[3 * SIMN + i]);
    __syncthreads();

    // softmax over 81 taps: 8 lanes per pixel, butterfly reduce
    if (t < 256) {
        const int px = t >> 3;
        const int q  = t & 7;
        float* srow = &simp[px * KK];
        float m = -1e30f;
        for (int k = q; k < KK; k += 8) m = fmaxf(m, srow[k]);
        m = fmaxf(m, __shfl_xor_sync(0xffffffffu, m, 1));
        m = fmaxf(m, __shfl_xor_sync(0xffffffffu, m, 2));
        m = fmaxf(m, __shfl_xor_sync(0xffffffffu, m, 4));
        float s = 0.f;
        for (int k = q; k < KK; k += 8) {
            float e = __expf(srow[k] - m);
            srow[k] = e;
            s += e;
        }
        s += __shfl_xor_sync(0xffffffffu, s, 1);
        s += __shfl_xor_sync(0xffffffffu, s, 2);
        s += __shfl_xor_sync(0xffffffffu, s, 4);
        const float inv = 1.f / s;
        float* wout = &g_weight[((n * H + ty0 + (px >> 4)) * WID + tx0 + (px & 15)) * KK];
        for (int k = q; k < KK; k += 8) wout[k] = srow[k] * inv;
    }
}

// ---------------------------------------------------------------------------
// Kernel D: out[c][p] = sum_k weight[p][k] * ft[c][p + off_k]  (zero-padded)
// grid = (128 tiles, 4 channel chunks), 256 threads. FFMA2 over px pairs.
// ---------------------------------------------------------------------------
__global__ __launch_bounds__(256) void weight_kernel(
        const float* __restrict__ ft, float* __restrict__ out)
{
    extern __shared__ float sm[];
    float* fts = sm;                    // CCD*HY*KST = 10752 floats
    float* ws  = fts + CCD * HY * KST;  // KK*WST     =  5508

    const int t   = threadIdx.x;
    const int bx  = blockIdx.x;
    const int n   = bx >> 6;
    const int rem = bx & 63;
    const int ty0 = (rem >> 2) * TH;
    const int tx0 = (rem & 3) * TW;
    const int c0  = blockIdx.y * CCD;
    const float* ftn = ft + n * C * HW;

    for (int i = t; i < TP * KK; i += 256) {
        int k  = i % KK;
        int px = i / KK;
        ws[k * WST + px] =
            g_weight[((n * H + ty0 + (px >> 4)) * WID + tx0 + (px & 15)) * KK + k];
    }
    for (int i = t; i < CCD * HY * HX; i += 256) {
        int hx = i % HX;
        int hy = (i / HX) % HY;
        int c  = i / (HX * HY);
        int gy = ty0 + hy - PADR;
        int gx = tx0 + hx - PADR;
        float v = 0.f;
        if ((unsigned)gy < H && (unsigned)gx < WID)
            v = ftn[(c0 + c) * HW + gy * WID + gx];
        fts[c * (HY * KST) + hy * KST + hx] = v;
    }
    __syncthreads();

    const int pxg = t & 15;
    const int cl  = (t >> 4) * 2;
    const int ly  = pxg >> 2;
    const int lxg = (pxg & 3) * 4;
    u64 ap0[2] = {}, ap1[2] = {};       // two channels x two px pairs

    #pragma unroll
    for (int di = 0; di < 9; di++) {
        const float* f0 = &fts[cl * (HY * KST) + (ly + di) * KST + lxg];
        const float* f1 = f0 + HY * KST;
        float4 x0 = *(const float4*)f0;
        float4 x1 = *(const float4*)(f0 + 4);
        float4 x2 = *(const float4*)(f0 + 8);
        float4 y0 = *(const float4*)f1;
        float4 y1 = *(const float4*)(f1 + 4);
        float4 y2 = *(const float4*)(f1 + 8);
        const float fr0[12] = {x0.x, x0.y, x0.z, x0.w, x1.x, x1.y, x1.z, x1.w,
                               x2.x, x2.y, x2.z, x2.w};
        const float fr1[12] = {y0.x, y0.y, y0.z, y0.w, y1.x, y1.y, y1.z, y1.w,
                               y2.x, y2.y, y2.z, y2.w};
        u64 w0[11], w1[11];
        #pragma unroll
        for (int m = 0; m < 11; m++) {
            w0[m] = pk(fr0[m], fr0[m + 1]);
            w1[m] = pk(fr1[m], fr1[m + 1]);
        }
        #pragma unroll
        for (int dj = 0; dj < 9; dj++) {
            float4 w4 = *(const float4*)&ws[(di * 9 + dj) * WST + ly * TW + lxg];
            u64 w01 = pk(w4.x, w4.y), w23 = pk(w4.z, w4.w);
            fma2(ap0[0], w01, w0[dj]);
            fma2(ap0[1], w23, w0[dj + 2]);
            fma2(ap1[0], w01, w1[dj]);
            fma2(ap1[1], w23, w1[dj + 2]);
        }
    }

    float* on = out + n * C * HW;
    const int pix = (ty0 + ly) * WID + tx0 + lxg;
    {
        float2 v0 = upk(ap0[0]), v1 = upk(ap0[1]);
        *(float4*)&on[(c0 + cl) * HW + pix] = make_float4(v0.x, v0.y, v1.x, v1.y);
    }
    {
        float2 v0 = upk(ap1[0]), v1 = upk(ap1[1]);
        *(float4*)&on[(c0 + cl + 1) * HW + pix] = make_float4(v0.x, v0.y, v1.x, v1.y);
    }
}

// ---------------------------------------------------------------------------
extern "C" void kernel_launch(void* const* d_in, const int* in_sizes, int n_in,
                              void* d_out, int out_size)
{
    const float* ft = (const float*)d_in[0];
    const float* fk = (const float*)d_in[1];
    const float* Wm = (const float*)d_in[2];
    float* out = (float*)d_out;

    const int smA = (128 * 64 + 2 * GK * GO) * (int)sizeof(float);             // 40960
    const int smB = (CCB * BHY * BKST + CCB * BTP + 4 * SIMN) * (int)sizeof(float); // 81408
    const int smD = (CCD * HY * KST + KK * WST) * (int)sizeof(float);          // 65040
    cudaFuncSetAttribute(gemm_kernel,
                         cudaFuncAttributeMaxDynamicSharedMemorySize, smA);
    cudaFuncSetAttribute(sim_softmax_kernel,
                         cudaFuncAttributeMaxDynamicSharedMemorySize, smB);
    cudaFuncSetAttribute(weight_kernel,
                         cudaFuncAttributeMaxDynamicSharedMemorySize, smD);

    gemm_kernel<<<dim3(HW / 64, 8), 256, smA>>>(ft, fk, Wm);
    sim_softmax_kernel<<<NB * (H / BTH) * (WID / BTW), BNT, smB>>>();
    weight_kernel<<<dim3(NB * (H / TH) * (WID / TW), C / CCD), 256, smD>>>(ft, out);
}